// round 10
// baseline (speedup 1.0000x reference)
#include <cuda_runtime.h>
#include <cuda_fp16.h>
#include <math.h>
#include <stdint.h>

#define T_ 4096
#define I_ 2048
#define HD 2048
#define K_ 3
#define NCOL 18432            // 3*3H
#define LO_SCALE 2048.0f      // lo pre-scale (2^11): keeps correction products normal-range
#define INV_LO   (1.0f / 2048.0f)

// ---------------- scratch (device globals) ---------------------------------
__device__ float g_gi[(size_t)T_ * NCOL];        // raw GEMM out ~302MB
__device__ float g_Hall[(size_t)T_ * K_ * HD];   // ~100.7MB
__device__ __half g_xhi[(size_t)T_ * I_];
__device__ __half g_xlo[(size_t)T_ * I_];        // scaled by 2^11
__device__ __half g_whi[(size_t)NCOL * I_];
__device__ __half g_wlo[(size_t)NCOL * I_];      // scaled by 2^11
__device__ float g_D[(size_t)T_ * K_ * K_];
__device__ float g_selx[(size_t)T_ * K_];
__device__ unsigned int g_fw[T_];
__device__ int g_kk[T_];

// ---------------- helpers ---------------------------------------------------
__device__ __forceinline__ uint32_t smem_u32(const void* p) {
    uint32_t a;
    asm("{ .reg .u64 t; cvta.to.shared.u64 t, %1; cvt.u32.u64 %0, t; }" : "=r"(a) : "l"(p));
    return a;
}
__device__ __forceinline__ void cp16(uint32_t s, const void* g) {
    asm volatile("cp.async.cg.shared.global [%0], [%1], 16;" :: "r"(s), "l"(g));
}
#define CP_COMMIT() asm volatile("cp.async.commit_group;" ::: "memory")
#define CP_WAIT0()  asm volatile("cp.async.wait_group 0;" ::: "memory")

__device__ __forceinline__ void ldsm_x4(uint32_t& r0, uint32_t& r1, uint32_t& r2,
                                        uint32_t& r3, uint32_t a) {
    asm volatile("ldmatrix.sync.aligned.m8n8.x4.shared.b16 {%0,%1,%2,%3}, [%4];"
                 : "=r"(r0), "=r"(r1), "=r"(r2), "=r"(r3) : "r"(a));
}
// fp32-accumulate HMMA (main hi*hi product)
__device__ __forceinline__ void mma16816(float* d, const uint32_t* a, uint32_t b0, uint32_t b1) {
    asm volatile("mma.sync.aligned.m16n8k16.row.col.f32.f16.f16.f32 "
                 "{%0,%1,%2,%3}, {%4,%5,%6,%7}, {%8,%9}, {%0,%1,%2,%3};"
                 : "+f"(d[0]), "+f"(d[1]), "+f"(d[2]), "+f"(d[3])
                 : "r"(a[0]), "r"(a[1]), "r"(a[2]), "r"(a[3]), "r"(b0), "r"(b1));
}
// fp16-accumulate HMMA (correction products; possibly double-rate)
__device__ __forceinline__ void mma16816_h(uint32_t& d0, uint32_t& d1, const uint32_t* a,
                                           uint32_t b0, uint32_t b1, uint32_t c0, uint32_t c1) {
    asm volatile("mma.sync.aligned.m16n8k16.row.col.f16.f16.f16.f16 "
                 "{%0,%1}, {%2,%3,%4,%5}, {%6,%7}, {%8,%9};"
                 : "=r"(d0), "=r"(d1)
                 : "r"(a[0]), "r"(a[1]), "r"(a[2]), "r"(a[3]),
                   "r"(b0), "r"(b1), "r"(c0), "r"(c1));
}

// ---------------------------------------------------------------------------
// K0: fp16 two-way split prep. hi = rn(x); lo = rn((x - hi) * 2^11).
// ---------------------------------------------------------------------------
__global__ __launch_bounds__(256) void k0_split(
    const float* __restrict__ src, __half* __restrict__ hi,
    __half* __restrict__ lo, size_t n4)
{
    size_t i = (size_t)blockIdx.x * 256 + threadIdx.x;
    if (i >= n4) return;
    float4 v = *(const float4*)(src + i * 4);
    __half h[4], l[4];
    float vv[4] = {v.x, v.y, v.z, v.w};
#pragma unroll
    for (int q = 0; q < 4; q++) {
        h[q] = __float2half_rn(vv[q]);
        l[q] = __float2half_rn((vv[q] - __half2float(h[q])) * LO_SCALE);
    }
    *(uint2*)(hi + i * 4) = *(uint2*)h;
    *(uint2*)(lo + i * 4) = *(uint2*)l;
}

// ---------------------------------------------------------------------------
// K1: C[4096,18432] = x @ Wih^T, f16x3 split.
//   hi*hi      -> fp32-accumulate HMMA (persistent acc)
//   hi*lo+lo*hi-> fp16-accumulate HMMA chain (2 mmas), folded into the fp32
//                 acc each (i,j) with *2^-11  (lo operands pre-scaled 2^11)
// CTA 128x128, double-buffered cp.async (2 stages, 80KB -> 2 CTAs/SM),
// per-group B fragment loads (8 live frag regs) to stay under 128 regs.
// ---------------------------------------------------------------------------
#define BK 32
#define ROWB 80
#define TILEB (128 * ROWB)        // 10240
#define STAGEB (4 * TILEB)        // 40960
#define NSTG 2
#define K1_SMEM (NSTG * STAGEB)   // 81920 -> two CTAs per SM
#define NS (I_ / BK)              // 64

__global__ void __launch_bounds__(256, 2) k1_mma(
    const __half* __restrict__ xhi, const __half* __restrict__ xlo,
    const __half* __restrict__ whi, const __half* __restrict__ wlo)
{
    extern __shared__ char smem[];
    const uint32_t sbase = smem_u32(smem);
    const int tid = threadIdx.x;
    const int wid = tid >> 5;
    const int lane = tid & 31;

    const int t0 = blockIdx.x * 128;   // M
    const int c0 = blockIdx.y * 128;   // N

    const int warpM = (wid & 3) * 32;
    const int warpN = (wid >> 2) * 64;

    float acc[2][8][4];
#pragma unroll
    for (int i = 0; i < 2; i++)
#pragma unroll
        for (int j = 0; j < 8; j++)
#pragma unroll
            for (int q = 0; q < 4; q++) acc[i][j][q] = 0.f;

    auto fetch = [&](int s) {
        const int stg = s & 1;
        const uint32_t bA_hi = sbase + stg * STAGEB;
        const uint32_t bA_lo = bA_hi + TILEB;
        const uint32_t bB_hi = bA_hi + 2 * TILEB;
        const uint32_t bB_lo = bA_hi + 3 * TILEB;
        const int k0 = s * BK;
#pragma unroll
        for (int it = 0; it < 2; it++) {
            int c = it * 256 + tid;
            int kc = c >> 7;
            int row = c & 127;
            uint32_t so = (uint32_t)(row * ROWB + kc * 16);
            size_t ga = (size_t)(t0 + row) * I_ + k0 + kc * 8;
            size_t gb = (size_t)(c0 + row) * I_ + k0 + kc * 8;
            cp16(bA_hi + so, xhi + ga);
            cp16(bA_lo + so, xlo + ga);
            cp16(bB_hi + so, whi + gb);
            cp16(bB_lo + so, wlo + gb);
        }
    };

    fetch(0); CP_COMMIT();

    for (int s = 0; s < NS; s++) {
        CP_WAIT0();          // stage s data landed
        __syncthreads();     // publish; all warps done with the other buffer

        if (s + 1 < NS) { fetch(s + 1); CP_COMMIT(); }  // async during compute

        const int stg = s & 1;
        const uint32_t bA_hi = sbase + stg * STAGEB;
        const uint32_t bA_lo = bA_hi + TILEB;
        const uint32_t bB_hi = bA_hi + 2 * TILEB;
        const uint32_t bB_lo = bA_hi + 3 * TILEB;

#pragma unroll
        for (int kc = 0; kc < 2; kc++) {
            const uint32_t kb = kc * 32 + (lane >> 4) * 16;
            const uint32_t rsel = (lane & 15);

            uint32_t Ah[2][4], Al[2][4];
#pragma unroll
            for (int i = 0; i < 2; i++) {
                uint32_t off = (uint32_t)((warpM + i * 16 + rsel) * ROWB) + kb;
                ldsm_x4(Ah[i][0], Ah[i][1], Ah[i][2], Ah[i][3], bA_hi + off);
                ldsm_x4(Al[i][0], Al[i][1], Al[i][2], Al[i][3], bA_lo + off);
            }
#pragma unroll
            for (int g = 0; g < 4; g++) {
                uint32_t Bhg[4], Blg[4];
                uint32_t off = (uint32_t)((warpN + g * 16 + rsel) * ROWB) + kb;
                ldsm_x4(Bhg[0], Bhg[1], Bhg[2], Bhg[3], bB_hi + off);
                ldsm_x4(Blg[0], Blg[1], Blg[2], Blg[3], bB_lo + off);
#pragma unroll
                for (int i = 0; i < 2; i++) {
#pragma unroll
                    for (int sel = 0; sel < 2; sel++) {
                        const int j = g * 2 + sel;
                        uint32_t bh0 = Bhg[sel], bh1 = Bhg[sel + 2];
                        uint32_t bl0 = Blg[sel], bl1 = Blg[sel + 2];
                        // main product: fp32 accumulate
                        mma16816(acc[i][j], Ah[i], bh0, bh1);
                        // corrections: f16 accumulate, chained, then fold
                        uint32_t d0, d1;
                        mma16816_h(d0, d1, Ah[i], bl0, bl1, 0u, 0u);  // hi*lo_s
                        mma16816_h(d0, d1, Al[i], bh0, bh1, d0, d1);  // + lo_s*hi
                        float2 f0 = __half22float2(*reinterpret_cast<__half2*>(&d0));
                        float2 f1 = __half22float2(*reinterpret_cast<__half2*>(&d1));
                        acc[i][j][0] = fmaf(f0.x, INV_LO, acc[i][j][0]);
                        acc[i][j][1] = fmaf(f0.y, INV_LO, acc[i][j][1]);
                        acc[i][j][2] = fmaf(f1.x, INV_LO, acc[i][j][2]);
                        acc[i][j][3] = fmaf(f1.y, INV_LO, acc[i][j][3]);
                    }
                }
            }
        }
    }

    // epilogue: acc -> g_gi
#pragma unroll
    for (int i = 0; i < 2; i++) {
#pragma unroll
        for (int j = 0; j < 8; j++) {
            int row = t0 + warpM + i * 16 + (lane >> 2);
            int col = c0 + warpN + j * 8 + (lane & 3) * 2;
            float2 u0 = make_float2(acc[i][j][0], acc[i][j][1]);
            float2 u1 = make_float2(acc[i][j][2], acc[i][j][3]);
            *(float2*)&g_gi[(size_t)row * NCOL + col] = u0;
            *(float2*)&g_gi[(size_t)(row + 8) * NCOL + col] = u1;
        }
    }
}

// ---------------------------------------------------------------------------
// K1b: elementwise gates  Hall[t][k][o]
// ---------------------------------------------------------------------------
__global__ __launch_bounds__(256) void k_gates(
    const float* __restrict__ bih, const float* __restrict__ bhh)
{
    size_t idx = (size_t)blockIdx.x * 256 + threadIdx.x;
    int o4 = (int)(idx % (HD / 4));
    int k  = (int)((idx / (HD / 4)) % K_);
    int t  = (int)(idx / ((size_t)K_ * (HD / 4)));

    const float* base = g_gi + (size_t)t * NCOL + (size_t)k * 3 * HD + o4 * 4;
    float4 ir4 = *(const float4*)(base);
    float4 iz4 = *(const float4*)(base + HD);
    float4 in4 = *(const float4*)(base + 2 * HD);

    const float* bi = bih + (size_t)k * 3 * HD;
    const float* bh = bhh + (size_t)k * 3 * HD;
    float4 br = *(const float4*)(bi + o4 * 4);
    float4 bz = *(const float4*)(bi + HD + o4 * 4);
    float4 bn = *(const float4*)(bi + 2 * HD + o4 * 4);
    float4 hr = *(const float4*)(bh + o4 * 4);
    float4 hz = *(const float4*)(bh + HD + o4 * 4);
    float4 hn = *(const float4*)(bh + 2 * HD + o4 * 4);

    float irs[4] = {ir4.x, ir4.y, ir4.z, ir4.w};
    float izs[4] = {iz4.x, iz4.y, iz4.z, iz4.w};
    float ins[4] = {in4.x, in4.y, in4.z, in4.w};
    float brs[4] = {br.x, br.y, br.z, br.w};
    float bzs[4] = {bz.x, bz.y, bz.z, bz.w};
    float bns[4] = {bn.x, bn.y, bn.z, bn.w};
    float hrs[4] = {hr.x, hr.y, hr.z, hr.w};
    float hzs[4] = {hz.x, hz.y, hz.z, hz.w};
    float hns[4] = {hn.x, hn.y, hn.z, hn.w};

    float res[4];
#pragma unroll
    for (int n = 0; n < 4; n++) {
        float r = 1.0f / (1.0f + expf(-(irs[n] + brs[n] + hrs[n])));
        float z = 1.0f / (1.0f + expf(-(izs[n] + bzs[n] + hzs[n])));
        float nn = tanhf(ins[n] + bns[n] + r * hns[n]);
        res[n] = (1.0f - z) * nn;
    }
    float4 o;
    o.x = res[0]; o.y = res[1]; o.z = res[2]; o.w = res[3];
    *(float4*)&g_Hall[((size_t)t * K_ + k) * HD + o4 * 4] = o;
}

// ---------------------------------------------------------------------------
// K2: D + sel_x
// ---------------------------------------------------------------------------
__global__ __launch_bounds__(256) void k2_Dselx(
    const float* __restrict__ xs, const float* __restrict__ Wsel,
    const float* __restrict__ bsel)
{
    const int t = blockIdx.x;
    float aD[9] = {0.f, 0.f, 0.f, 0.f, 0.f, 0.f, 0.f, 0.f, 0.f};
    float aS[3] = {0.f, 0.f, 0.f};

    const float* hrow = g_Hall + (size_t)t * K_ * HD;
    const float* xrow = xs + (size_t)t * I_;
    const int WS = HD + I_;

    for (int h = threadIdx.x; h < HD; h += 256) {
        float w0 = Wsel[0 * WS + h];
        float w1 = Wsel[1 * WS + h];
        float w2 = Wsel[2 * WS + h];
#pragma unroll
        for (int j = 0; j < 3; j++) {
            float hv = hrow[(size_t)j * HD + h];
            aD[j * 3 + 0] = fmaf(hv, w0, aD[j * 3 + 0]);
            aD[j * 3 + 1] = fmaf(hv, w1, aD[j * 3 + 1]);
            aD[j * 3 + 2] = fmaf(hv, w2, aD[j * 3 + 2]);
        }
    }
    for (int i = threadIdx.x; i < I_; i += 256) {
        float xv = xrow[i];
        aS[0] = fmaf(xv, Wsel[0 * WS + HD + i], aS[0]);
        aS[1] = fmaf(xv, Wsel[1 * WS + HD + i], aS[1]);
        aS[2] = fmaf(xv, Wsel[2 * WS + HD + i], aS[2]);
    }

    float vals[12];
#pragma unroll
    for (int v = 0; v < 9; v++) vals[v] = aD[v];
#pragma unroll
    for (int v = 0; v < 3; v++) vals[9 + v] = aS[v];

    __shared__ float red[12][8];
    int lane = threadIdx.x & 31, w = threadIdx.x >> 5;
#pragma unroll
    for (int v = 0; v < 12; v++) {
        float s = vals[v];
        for (int off = 16; off > 0; off >>= 1)
            s += __shfl_down_sync(0xffffffffu, s, off);
        if (lane == 0) red[v][w] = s;
    }
    __syncthreads();
    if (threadIdx.x < 12) {
        float s = 0.f;
#pragma unroll
        for (int ww = 0; ww < 8; ww++) s += red[threadIdx.x][ww];
        if (threadIdx.x < 9)
            g_D[(size_t)t * 9 + threadIdx.x] = s;
        else
            g_selx[(size_t)t * 3 + (threadIdx.x - 9)] = s + bsel[threadIdx.x - 9];
    }
}

// ---------------------------------------------------------------------------
// K3: packed transition maps
// ---------------------------------------------------------------------------
__global__ void k3_f()
{
    int t = blockIdx.x * blockDim.x + threadIdx.x;
    if (t < 1 || t >= T_) return;
    const float* d = g_D + (size_t)(t - 1) * 9;
    float s0 = g_selx[t * 3 + 0];
    float s1 = g_selx[t * 3 + 1];
    float s2 = g_selx[t * 3 + 2];
    unsigned int word = 0;
#pragma unroll
    for (int j = 0; j < 3; j++) {
        float l0 = d[j * 3 + 0] + s0;
        float l1 = d[j * 3 + 1] + s1;
        float l2 = d[j * 3 + 2] + s2;
        int best = 0; float bv = l0;
        if (l1 > bv) { bv = l1; best = 1; }
        if (l2 > bv) { best = 2; }
        word |= (unsigned int)best << (8 * j);
    }
    g_fw[t] = word;
}

// ---------------------------------------------------------------------------
// K4: sequential 3-state automaton composition
// ---------------------------------------------------------------------------
__global__ __launch_bounds__(256) void k4_scan()
{
    __shared__ unsigned int sw[T_];
    for (int i = threadIdx.x; i < T_; i += 256) sw[i] = g_fw[i];
    __syncthreads();
    if (threadIdx.x == 0) {
        int cur = 0;
        g_kk[0] = 0;
        for (int t = 1; t < T_; t++) {
            unsigned int w = sw[t];
            cur = (int)((w >> (cur << 3)) & 0xffu);
            g_kk[t] = cur;
        }
    }
}

// ---------------------------------------------------------------------------
// K5: gather
// ---------------------------------------------------------------------------
__global__ __launch_bounds__(256) void k5_gather(float* __restrict__ out)
{
    int t = blockIdx.x;
    int tt = (t == T_) ? (T_ - 1) : t;
    int sel = g_kk[tt];
    const float4* src = (const float4*)(g_Hall + ((size_t)tt * K_ + sel) * HD);
    float4* dst = (float4*)(out + (size_t)t * HD);
    for (int i = threadIdx.x; i < HD / 4; i += 256) dst[i] = src[i];
}

// ---------------------------------------------------------------------------
extern "C" void kernel_launch(void* const* d_in, const int* in_sizes, int n_in,
                              void* d_out, int out_size)
{
    const float* x    = (const float*)d_in[0];
    const float* Wih  = (const float*)d_in[1];
    // d_in[2] = W_hh : unused (only b_hh enters the math)
    const float* bih  = (const float*)d_in[3];
    const float* bhh  = (const float*)d_in[4];
    const float* Wsel = (const float*)d_in[5];
    const float* bsel = (const float*)d_in[6];
    float* out = (float*)d_out;

    __half *xhi, *xlo, *whi, *wlo;
    cudaGetSymbolAddress((void**)&xhi, g_xhi);
    cudaGetSymbolAddress((void**)&xlo, g_xlo);
    cudaGetSymbolAddress((void**)&whi, g_whi);
    cudaGetSymbolAddress((void**)&wlo, g_wlo);

    cudaFuncSetAttribute(k1_mma, cudaFuncAttributeMaxDynamicSharedMemorySize, K1_SMEM);

    size_t nx4 = (size_t)T_ * I_ / 4;
    size_t nw4 = (size_t)NCOL * I_ / 4;
    k0_split<<<(int)((nx4 + 255) / 256), 256>>>(x, xhi, xlo, nx4);
    k0_split<<<(int)((nw4 + 255) / 256), 256>>>(Wih, whi, wlo, nw4);

    dim3 g1(T_ / 128, NCOL / 128);  // (32, 144), M-fast -> A stays L2-resident
    k1_mma<<<g1, 256, K1_SMEM>>>(xhi, xlo, whi, wlo);

    k_gates<<<(int)(((size_t)T_ * K_ * (HD / 4)) / 256), 256>>>(bih, bhh);
    k2_Dselx<<<T_, 256>>>(x, Wsel, bsel);
    k3_f<<<(T_ + 255) / 256, 256>>>();
    k4_scan<<<1, 256>>>();
    k5_gather<<<T_ + 1, 256>>>(out);
}

// round 11
// speedup vs baseline: 1.2949x; 1.2949x over previous
#include <cuda_runtime.h>
#include <cuda_fp16.h>
#include <math.h>
#include <stdint.h>

#define T_ 4096
#define I_ 2048
#define HD 2048
#define K_ 3
#define NCOL 18432            // 3*3H
#define WS_ (HD + I_)
#define THETA 4e-3f           // ambiguity threshold on top-2 logit gap (~11 sigma)
#define MAXF 64               // max flagged steps (expected ~16)

// ---------------- scratch (device globals) ---------------------------------
__device__ float g_gi[(size_t)T_ * NCOL];        // 2-product GEMM out ~302MB
__device__ float g_Hall[(size_t)T_ * K_ * HD];   // ~100.7MB
__device__ __half g_xhi[(size_t)T_ * I_];
__device__ __half g_xlo[(size_t)T_ * I_];
__device__ __half g_whi[(size_t)NCOL * I_];
__device__ float g_D[(size_t)T_ * K_ * K_];
__device__ float g_selx[(size_t)T_ * K_];
__device__ float g_dfix[(size_t)MAXF * NCOL];    // exact corrections for flagged rows
__device__ int g_fixn;
__device__ int g_fixlist[MAXF];
__device__ unsigned int g_fw[T_];
__device__ int g_kk[T_];

// ---------------- helpers ---------------------------------------------------
__device__ __forceinline__ uint32_t smem_u32(const void* p) {
    uint32_t a;
    asm("{ .reg .u64 t; cvta.to.shared.u64 t, %1; cvt.u32.u64 %0, t; }" : "=r"(a) : "l"(p));
    return a;
}
__device__ __forceinline__ void cp16(uint32_t s, const void* g) {
    asm volatile("cp.async.cg.shared.global [%0], [%1], 16;" :: "r"(s), "l"(g));
}
#define CP_COMMIT() asm volatile("cp.async.commit_group;" ::: "memory")
#define CP_WAIT0()  asm volatile("cp.async.wait_group 0;" ::: "memory")

__device__ __forceinline__ void ldsm_x4(uint32_t& r0, uint32_t& r1, uint32_t& r2,
                                        uint32_t& r3, uint32_t a) {
    asm volatile("ldmatrix.sync.aligned.m8n8.x4.shared.b16 {%0,%1,%2,%3}, [%4];"
                 : "=r"(r0), "=r"(r1), "=r"(r2), "=r"(r3) : "r"(a));
}
__device__ __forceinline__ void mma16816(float* d, const uint32_t* a, uint32_t b0, uint32_t b1) {
    asm volatile("mma.sync.aligned.m16n8k16.row.col.f32.f16.f16.f32 "
                 "{%0,%1,%2,%3}, {%4,%5,%6,%7}, {%8,%9}, {%0,%1,%2,%3};"
                 : "+f"(d[0]), "+f"(d[1]), "+f"(d[2]), "+f"(d[3])
                 : "r"(a[0]), "r"(a[1]), "r"(a[2]), "r"(a[3]), "r"(b0), "r"(b1));
}

// ---------------------------------------------------------------------------
// K0a: x -> (xhi, xlo).   K0b: W -> whi only.
// ---------------------------------------------------------------------------
__global__ __launch_bounds__(256) void k0_split(
    const float* __restrict__ src, __half* __restrict__ hi,
    __half* __restrict__ lo, size_t n4)
{
    size_t i = (size_t)blockIdx.x * 256 + threadIdx.x;
    if (i >= n4) return;
    float4 v = *(const float4*)(src + i * 4);
    __half h[4], l[4];
    float vv[4] = {v.x, v.y, v.z, v.w};
#pragma unroll
    for (int q = 0; q < 4; q++) {
        h[q] = __float2half_rn(vv[q]);
        l[q] = __float2half_rn(vv[q] - __half2float(h[q]));
    }
    *(uint2*)(hi + i * 4) = *(uint2*)h;
    *(uint2*)(lo + i * 4) = *(uint2*)l;
}

__global__ __launch_bounds__(256) void k0_half(
    const float* __restrict__ src, __half* __restrict__ hi, size_t n4)
{
    size_t i = (size_t)blockIdx.x * 256 + threadIdx.x;
    if (i >= n4) return;
    float4 v = *(const float4*)(src + i * 4);
    __half h[4];
    h[0] = __float2half_rn(v.x); h[1] = __float2half_rn(v.y);
    h[2] = __float2half_rn(v.z); h[3] = __float2half_rn(v.w);
    *(uint2*)(hi + i * 4) = *(uint2*)h;
}

// ---------------------------------------------------------------------------
// K1: gi = (xhi+xlo) @ whi^T  -- 2 HMMA products per tile-op (was 3).
// CTA 128x128, double-buffered cp.async (2 stages x 3 buffers = 60KB ->
// 2 CTAs/SM), one __syncthreads per stage.
// ---------------------------------------------------------------------------
#define BK 32
#define ROWB 80
#define TILEB (128 * ROWB)        // 10240
#define STAGEB (3 * TILEB)        // 30720 (A_hi, A_lo, B_hi)
#define K1_SMEM (2 * STAGEB)      // 61440
#define NS (I_ / BK)              // 64

__global__ void __launch_bounds__(256, 2) k1_mma(
    const __half* __restrict__ xhi, const __half* __restrict__ xlo,
    const __half* __restrict__ whi)
{
    extern __shared__ char smem[];
    const uint32_t sbase = smem_u32(smem);
    const int tid = threadIdx.x;
    const int wid = tid >> 5;
    const int lane = tid & 31;

    const int t0 = blockIdx.x * 128;   // M
    const int c0 = blockIdx.y * 128;   // N

    const int warpM = (wid & 3) * 32;
    const int warpN = (wid >> 2) * 64;

    float acc[2][8][4];
#pragma unroll
    for (int i = 0; i < 2; i++)
#pragma unroll
        for (int j = 0; j < 8; j++)
#pragma unroll
            for (int q = 0; q < 4; q++) acc[i][j][q] = 0.f;

    auto fetch = [&](int s) {
        const int stg = s & 1;
        const uint32_t bA_hi = sbase + stg * STAGEB;
        const uint32_t bA_lo = bA_hi + TILEB;
        const uint32_t bB_hi = bA_hi + 2 * TILEB;
        const int k0 = s * BK;
#pragma unroll
        for (int it = 0; it < 2; it++) {
            int c = it * 256 + tid;
            int kc = c >> 7;
            int row = c & 127;
            uint32_t so = (uint32_t)(row * ROWB + kc * 16);
            size_t ga = (size_t)(t0 + row) * I_ + k0 + kc * 8;
            size_t gb = (size_t)(c0 + row) * I_ + k0 + kc * 8;
            cp16(bA_hi + so, xhi + ga);
            cp16(bA_lo + so, xlo + ga);
            cp16(bB_hi + so, whi + gb);
        }
    };

    fetch(0); CP_COMMIT();

    for (int s = 0; s < NS; s++) {
        CP_WAIT0();
        __syncthreads();

        if (s + 1 < NS) { fetch(s + 1); CP_COMMIT(); }

        const int stg = s & 1;
        const uint32_t bA_hi = sbase + stg * STAGEB;
        const uint32_t bA_lo = bA_hi + TILEB;
        const uint32_t bB_hi = bA_hi + 2 * TILEB;

#pragma unroll
        for (int kc = 0; kc < 2; kc++) {
            const uint32_t kb = kc * 32 + (lane >> 4) * 16;
            const uint32_t rsel = (lane & 15);

            uint32_t Ah[2][4], Al[2][4];
#pragma unroll
            for (int i = 0; i < 2; i++) {
                uint32_t off = (uint32_t)((warpM + i * 16 + rsel) * ROWB) + kb;
                ldsm_x4(Ah[i][0], Ah[i][1], Ah[i][2], Ah[i][3], bA_hi + off);
                ldsm_x4(Al[i][0], Al[i][1], Al[i][2], Al[i][3], bA_lo + off);
            }
#pragma unroll
            for (int g = 0; g < 4; g++) {
                uint32_t Bhg[4];
                uint32_t off = (uint32_t)((warpN + g * 16 + rsel) * ROWB) + kb;
                ldsm_x4(Bhg[0], Bhg[1], Bhg[2], Bhg[3], bB_hi + off);
#pragma unroll
                for (int i = 0; i < 2; i++) {
#pragma unroll
                    for (int sel = 0; sel < 2; sel++) {
                        const int j = g * 2 + sel;
                        mma16816(acc[i][j], Ah[i], Bhg[sel], Bhg[sel + 2]);
                        mma16816(acc[i][j], Al[i], Bhg[sel], Bhg[sel + 2]);
                    }
                }
            }
        }
    }

#pragma unroll
    for (int i = 0; i < 2; i++) {
#pragma unroll
        for (int j = 0; j < 8; j++) {
            int row = t0 + warpM + i * 16 + (lane >> 2);
            int col = c0 + warpN + j * 8 + (lane & 3) * 2;
            float2 u0 = make_float2(acc[i][j][0], acc[i][j][1]);
            float2 u1 = make_float2(acc[i][j][2], acc[i][j][3]);
            *(float2*)&g_gi[(size_t)row * NCOL + col] = u0;
            *(float2*)&g_gi[(size_t)(row + 8) * NCOL + col] = u1;
        }
    }
}

// ---------------------------------------------------------------------------
// gates: Hall[t][k][o]
// ---------------------------------------------------------------------------
__global__ __launch_bounds__(256) void k_gates(
    const float* __restrict__ bih, const float* __restrict__ bhh)
{
    size_t idx = (size_t)blockIdx.x * 256 + threadIdx.x;
    int o4 = (int)(idx % (HD / 4));
    int k  = (int)((idx / (HD / 4)) % K_);
    int t  = (int)(idx / ((size_t)K_ * (HD / 4)));

    const float* base = g_gi + (size_t)t * NCOL + (size_t)k * 3 * HD + o4 * 4;
    float4 ir4 = *(const float4*)(base);
    float4 iz4 = *(const float4*)(base + HD);
    float4 in4 = *(const float4*)(base + 2 * HD);

    const float* bi = bih + (size_t)k * 3 * HD;
    const float* bh = bhh + (size_t)k * 3 * HD;
    float4 br = *(const float4*)(bi + o4 * 4);
    float4 bz = *(const float4*)(bi + HD + o4 * 4);
    float4 bn = *(const float4*)(bi + 2 * HD + o4 * 4);
    float4 hr = *(const float4*)(bh + o4 * 4);
    float4 hz = *(const float4*)(bh + HD + o4 * 4);
    float4 hn = *(const float4*)(bh + 2 * HD + o4 * 4);

    float irs[4] = {ir4.x, ir4.y, ir4.z, ir4.w};
    float izs[4] = {iz4.x, iz4.y, iz4.z, iz4.w};
    float ins[4] = {in4.x, in4.y, in4.z, in4.w};
    float brs[4] = {br.x, br.y, br.z, br.w};
    float bzs[4] = {bz.x, bz.y, bz.z, bz.w};
    float bns[4] = {bn.x, bn.y, bn.z, bn.w};
    float hrs[4] = {hr.x, hr.y, hr.z, hr.w};
    float hzs[4] = {hz.x, hz.y, hz.z, hz.w};
    float hns[4] = {hn.x, hn.y, hn.z, hn.w};

    float res[4];
#pragma unroll
    for (int n = 0; n < 4; n++) {
        float r = 1.0f / (1.0f + expf(-(irs[n] + brs[n] + hrs[n])));
        float z = 1.0f / (1.0f + expf(-(izs[n] + bzs[n] + hzs[n])));
        float nn = tanhf(ins[n] + bns[n] + r * hns[n]);
        res[n] = (1.0f - z) * nn;
    }
    float4 o;
    o.x = res[0]; o.y = res[1]; o.z = res[2]; o.w = res[3];
    *(float4*)&g_Hall[((size_t)t * K_ + k) * HD + o4 * 4] = o;
}

// ---------------------------------------------------------------------------
// K2: D + sel_x
// ---------------------------------------------------------------------------
__global__ __launch_bounds__(256) void k2_Dselx(
    const float* __restrict__ xs, const float* __restrict__ Wsel,
    const float* __restrict__ bsel)
{
    const int t = blockIdx.x;
    float aD[9] = {0.f, 0.f, 0.f, 0.f, 0.f, 0.f, 0.f, 0.f, 0.f};
    float aS[3] = {0.f, 0.f, 0.f};

    const float* hrow = g_Hall + (size_t)t * K_ * HD;
    const float* xrow = xs + (size_t)t * I_;

    for (int h = threadIdx.x; h < HD; h += 256) {
        float w0 = Wsel[0 * WS_ + h];
        float w1 = Wsel[1 * WS_ + h];
        float w2 = Wsel[2 * WS_ + h];
#pragma unroll
        for (int j = 0; j < 3; j++) {
            float hv = hrow[(size_t)j * HD + h];
            aD[j * 3 + 0] = fmaf(hv, w0, aD[j * 3 + 0]);
            aD[j * 3 + 1] = fmaf(hv, w1, aD[j * 3 + 1]);
            aD[j * 3 + 2] = fmaf(hv, w2, aD[j * 3 + 2]);
        }
    }
    for (int i = threadIdx.x; i < I_; i += 256) {
        float xv = xrow[i];
        aS[0] = fmaf(xv, Wsel[0 * WS_ + HD + i], aS[0]);
        aS[1] = fmaf(xv, Wsel[1 * WS_ + HD + i], aS[1]);
        aS[2] = fmaf(xv, Wsel[2 * WS_ + HD + i], aS[2]);
    }

    float vals[12];
#pragma unroll
    for (int v = 0; v < 9; v++) vals[v] = aD[v];
#pragma unroll
    for (int v = 0; v < 3; v++) vals[9 + v] = aS[v];

    __shared__ float red[12][8];
    int lane = threadIdx.x & 31, w = threadIdx.x >> 5;
#pragma unroll
    for (int v = 0; v < 12; v++) {
        float s = vals[v];
        for (int off = 16; off > 0; off >>= 1)
            s += __shfl_down_sync(0xffffffffu, s, off);
        if (lane == 0) red[v][w] = s;
    }
    __syncthreads();
    if (threadIdx.x < 12) {
        float s = 0.f;
#pragma unroll
        for (int ww = 0; ww < 8; ww++) s += red[threadIdx.x][ww];
        if (threadIdx.x < 9)
            g_D[(size_t)t * 9 + threadIdx.x] = s;
        else
            g_selx[(size_t)t * 3 + (threadIdx.x - 9)] = s + bsel[threadIdx.x - 9];
    }
}

// ---------------------------------------------------------------------------
// reset fix counter (graph replays!)
// ---------------------------------------------------------------------------
__global__ void k_zero() { g_fixn = 0; }

// ---------------------------------------------------------------------------
// K3a: flag ambiguous steps (any j-row with top-2 gap < THETA) -> fixlist
// ---------------------------------------------------------------------------
__global__ void k3_flag()
{
    int t = blockIdx.x * blockDim.x + threadIdx.x;
    if (t < 1 || t >= T_) return;
    const float* d = g_D + (size_t)(t - 1) * 9;
    float s0 = g_selx[t * 3 + 0];
    float s1 = g_selx[t * 3 + 1];
    float s2 = g_selx[t * 3 + 2];
    bool amb = false;
#pragma unroll
    for (int j = 0; j < 3; j++) {
        float l0 = d[j * 3 + 0] + s0;
        float l1 = d[j * 3 + 1] + s1;
        float l2 = d[j * 3 + 2] + s2;
        float hi1 = fmaxf(l0, fmaxf(l1, l2));
        float lo1 = fminf(l0, fminf(l1, l2));
        float mid = l0 + l1 + l2 - hi1 - lo1;
        if (hi1 - mid < THETA) amb = true;
    }
    if (amb) {
        int idx = atomicAdd(&g_fixn, 1);
        if (idx < MAXF) g_fixlist[idx] = t - 1;   // D row to repair
    }
}

// ---------------------------------------------------------------------------
// K3b-fix1: batched correction GEMM for flagged rows.
// dfix[f][c] = sum_i x[t1[f]][i] * (W[c][i] - rn16(W[c][i]))
// grid (NCOL/128, MAXF/32), block 256. smem-staged W and x chunks.
// ---------------------------------------------------------------------------
__global__ __launch_bounds__(256) void k_fixgemm(
    const float* __restrict__ xs, const float* __restrict__ Wih)
{
    int n = g_fixn; if (n > MAXF) n = MAXF;
    const int fbase = blockIdx.y * 32;
    if (fbase >= n) return;
    const int c0 = blockIdx.x * 128;
    const int tid = threadIdx.x;

    __shared__ float ews[32][129];   // [k][c]
    __shared__ float xsm[32][33];    // [f][k]
    __shared__ int tlist[32];

    if (tid < 32) tlist[tid] = (fbase + tid < n) ? g_fixlist[fbase + tid] : -1;
    __syncthreads();

    const int c_loc = tid & 127;
    const int fgrp = (tid >> 7) * 16;

    float acc[16];
#pragma unroll
    for (int f = 0; f < 16; f++) acc[f] = 0.f;

    for (int kc0 = 0; kc0 < I_; kc0 += 32) {
        __syncthreads();
        // load W chunk (128 cols x 32 k), compute eps on the fly
#pragma unroll
        for (int q = 0; q < 16; q++) {
            int lin = q * 256 + tid;          // 0..4095
            int c = lin >> 5, k = lin & 31;
            float w = Wih[(size_t)(c0 + c) * I_ + kc0 + k];
            ews[k][c] = w - __half2float(__float2half_rn(w));
        }
        // load x chunk (32 f x 32 k)
#pragma unroll
        for (int q = 0; q < 4; q++) {
            int lin = q * 256 + tid;          // 0..1023
            int f = lin >> 5, k = lin & 31;
            int t1 = tlist[f];
            xsm[f][k] = (t1 >= 0) ? xs[(size_t)t1 * I_ + kc0 + k] : 0.f;
        }
        __syncthreads();

#pragma unroll 4
        for (int k = 0; k < 32; k++) {
            float w = ews[k][c_loc];
#pragma unroll
            for (int f = 0; f < 16; f++)
                acc[f] = fmaf(xsm[fgrp + f][k], w, acc[f]);
        }
    }

#pragma unroll
    for (int f = 0; f < 16; f++) {
        int fg = fbase + fgrp + f;
        if (fg < n) g_dfix[(size_t)fg * NCOL + c0 + c_loc] = acc[f];
    }
}

// ---------------------------------------------------------------------------
// K3b-fix2: recompute exact D rows for flagged steps.  grid (MAXF, 3).
// ---------------------------------------------------------------------------
__global__ __launch_bounds__(256) void k_fixD(
    const float* __restrict__ Wsel,
    const float* __restrict__ bih, const float* __restrict__ bhh)
{
    int n = g_fixn; if (n > MAXF) n = MAXF;
    const int fi = blockIdx.x;
    if (fi >= n) return;
    const int t1 = g_fixlist[fi];
    const int j = blockIdx.y;
    const int tid = threadIdx.x;

    const size_t gb = (size_t)t1 * NCOL + (size_t)j * 3 * HD;
    const size_t db = (size_t)fi * NCOL + (size_t)j * 3 * HD;
    const float* bi = bih + (size_t)j * 3 * HD;
    const float* bh = bhh + (size_t)j * 3 * HD;

    float p0 = 0.f, p1 = 0.f, p2 = 0.f;
    for (int o = tid; o < HD; o += 256) {
        float ir  = g_gi[gb + o]          + g_dfix[db + o]          + bi[o]          + bh[o];
        float iz  = g_gi[gb + HD + o]     + g_dfix[db + HD + o]     + bi[HD + o]     + bh[HD + o];
        float inn = g_gi[gb + 2 * HD + o] + g_dfix[db + 2 * HD + o] + bi[2 * HD + o];
        float hn  = bh[2 * HD + o];
        float r = 1.0f / (1.0f + expf(-ir));
        float z = 1.0f / (1.0f + expf(-iz));
        float nn = tanhf(inn + r * hn);
        float h = (1.0f - z) * nn;
        p0 = fmaf(Wsel[0 * WS_ + o], h, p0);
        p1 = fmaf(Wsel[1 * WS_ + o], h, p1);
        p2 = fmaf(Wsel[2 * WS_ + o], h, p2);
    }

    __shared__ float red[3][8];
    int lane = tid & 31, w = tid >> 5;
    float v[3] = {p0, p1, p2};
#pragma unroll
    for (int q = 0; q < 3; q++) {
        float s = v[q];
        for (int off = 16; off > 0; off >>= 1)
            s += __shfl_down_sync(0xffffffffu, s, off);
        if (lane == 0) red[q][w] = s;
    }
    __syncthreads();
    if (tid < 3) {
        float s = 0.f;
#pragma unroll
        for (int ww = 0; ww < 8; ww++) s += red[tid][ww];
        g_D[(size_t)t1 * 9 + j * 3 + tid] = s;
    }
}

// ---------------------------------------------------------------------------
// K3: packed transition maps (after D repair)
// ---------------------------------------------------------------------------
__global__ void k3_f()
{
    int t = blockIdx.x * blockDim.x + threadIdx.x;
    if (t < 1 || t >= T_) return;
    const float* d = g_D + (size_t)(t - 1) * 9;
    float s0 = g_selx[t * 3 + 0];
    float s1 = g_selx[t * 3 + 1];
    float s2 = g_selx[t * 3 + 2];
    unsigned int word = 0;
#pragma unroll
    for (int j = 0; j < 3; j++) {
        float l0 = d[j * 3 + 0] + s0;
        float l1 = d[j * 3 + 1] + s1;
        float l2 = d[j * 3 + 2] + s2;
        int best = 0; float bv = l0;
        if (l1 > bv) { bv = l1; best = 1; }
        if (l2 > bv) { best = 2; }
        word |= (unsigned int)best << (8 * j);
    }
    g_fw[t] = word;
}

// ---------------------------------------------------------------------------
// K4: sequential 3-state automaton composition
// ---------------------------------------------------------------------------
__global__ __launch_bounds__(256) void k4_scan()
{
    __shared__ unsigned int sw[T_];
    for (int i = threadIdx.x; i < T_; i += 256) sw[i] = g_fw[i];
    __syncthreads();
    if (threadIdx.x == 0) {
        int cur = 0;
        g_kk[0] = 0;
        for (int t = 1; t < T_; t++) {
            unsigned int w = sw[t];
            cur = (int)((w >> (cur << 3)) & 0xffu);
            g_kk[t] = cur;
        }
    }
}

// ---------------------------------------------------------------------------
// K5: gather
// ---------------------------------------------------------------------------
__global__ __launch_bounds__(256) void k5_gather(float* __restrict__ out)
{
    int t = blockIdx.x;
    int tt = (t == T_) ? (T_ - 1) : t;
    int sel = g_kk[tt];
    const float4* src = (const float4*)(g_Hall + ((size_t)tt * K_ + sel) * HD);
    float4* dst = (float4*)(out + (size_t)t * HD);
    for (int i = threadIdx.x; i < HD / 4; i += 256) dst[i] = src[i];
}

// ---------------------------------------------------------------------------
extern "C" void kernel_launch(void* const* d_in, const int* in_sizes, int n_in,
                              void* d_out, int out_size)
{
    const float* x    = (const float*)d_in[0];
    const float* Wih  = (const float*)d_in[1];
    // d_in[2] = W_hh : unused (only b_hh enters the math)
    const float* bih  = (const float*)d_in[3];
    const float* bhh  = (const float*)d_in[4];
    const float* Wsel = (const float*)d_in[5];
    const float* bsel = (const float*)d_in[6];
    float* out = (float*)d_out;

    __half *xhi, *xlo, *whi;
    cudaGetSymbolAddress((void**)&xhi, g_xhi);
    cudaGetSymbolAddress((void**)&xlo, g_xlo);
    cudaGetSymbolAddress((void**)&whi, g_whi);

    cudaFuncSetAttribute(k1_mma, cudaFuncAttributeMaxDynamicSharedMemorySize, K1_SMEM);

    size_t nx4 = (size_t)T_ * I_ / 4;
    size_t nw4 = (size_t)NCOL * I_ / 4;
    k0_split<<<(int)((nx4 + 255) / 256), 256>>>(x, xhi, xlo, nx4);
    k0_half<<<(int)((nw4 + 255) / 256), 256>>>(Wih, whi, nw4);

    dim3 g1(T_ / 128, NCOL / 128);  // M-fast -> A stays L2-resident
    k1_mma<<<g1, 256, K1_SMEM>>>(xhi, xlo, whi);

    k_gates<<<(int)(((size_t)T_ * K_ * (HD / 4)) / 256), 256>>>(bih, bhh);
    k2_Dselx<<<T_, 256>>>(x, Wsel, bsel);

    k_zero<<<1, 1>>>();
    k3_flag<<<(T_ + 255) / 256, 256>>>();
    {
        dim3 gf(NCOL / 128, MAXF / 32);
        k_fixgemm<<<gf, 256>>>(x, Wih);
    }
    {
        dim3 gd(MAXF, 3);
        k_fixD<<<gd, 256>>>(Wsel, bih, bhh);
    }
    k3_f<<<(T_ + 255) / 256, 256>>>();
    k4_scan<<<1, 256>>>();
    k5_gather<<<T_ + 1, 256>>>(out);
}

// round 12
// speedup vs baseline: 1.9511x; 1.5068x over previous
#include <cuda_runtime.h>
#include <cuda_fp16.h>
#include <math.h>
#include <stdint.h>

#define T_ 4096
#define I_ 2048
#define HD 2048
#define K_ 3
#define NCOL 18432            // 3*3H
#define WS_ (HD + I_)
#define THETA 4e-3f           // ambiguity threshold on top-2 logit gap (~9.3 sigma)
#define MAXF 128              // max flagged steps (expected ~16)

// ---------------- scratch (device globals) ---------------------------------
__device__ float g_gi[(size_t)T_ * NCOL];        // 1-product GEMM out ~302MB
__device__ float g_Hall[(size_t)T_ * K_ * HD];   // ~100.7MB
__device__ __half g_xhi[(size_t)T_ * I_];
__device__ __half g_whi[(size_t)NCOL * I_];
__device__ float g_D[(size_t)T_ * K_ * K_];
__device__ float g_selx[(size_t)T_ * K_];
__device__ float g_dfix[(size_t)MAXF * NCOL];    // exact corrections for flagged rows
__device__ int g_fixn;
__device__ int g_fixlist[MAXF];
__device__ unsigned int g_fw[T_];
__device__ int g_kk[T_];

// ---------------- helpers ---------------------------------------------------
__device__ __forceinline__ uint32_t smem_u32(const void* p) {
    uint32_t a;
    asm("{ .reg .u64 t; cvta.to.shared.u64 t, %1; cvt.u32.u64 %0, t; }" : "=r"(a) : "l"(p));
    return a;
}
__device__ __forceinline__ void cp16(uint32_t s, const void* g) {
    asm volatile("cp.async.cg.shared.global [%0], [%1], 16;" :: "r"(s), "l"(g));
}
#define CP_COMMIT() asm volatile("cp.async.commit_group;" ::: "memory")
#define CP_WAIT0()  asm volatile("cp.async.wait_group 0;" ::: "memory")

__device__ __forceinline__ void ldsm_x4(uint32_t& r0, uint32_t& r1, uint32_t& r2,
                                        uint32_t& r3, uint32_t a) {
    asm volatile("ldmatrix.sync.aligned.m8n8.x4.shared.b16 {%0,%1,%2,%3}, [%4];"
                 : "=r"(r0), "=r"(r1), "=r"(r2), "=r"(r3) : "r"(a));
}
__device__ __forceinline__ void mma16816(float* d, const uint32_t* a, uint32_t b0, uint32_t b1) {
    asm volatile("mma.sync.aligned.m16n8k16.row.col.f32.f16.f16.f32 "
                 "{%0,%1,%2,%3}, {%4,%5,%6,%7}, {%8,%9}, {%0,%1,%2,%3};"
                 : "+f"(d[0]), "+f"(d[1]), "+f"(d[2]), "+f"(d[3])
                 : "r"(a[0]), "r"(a[1]), "r"(a[2]), "r"(a[3]), "r"(b0), "r"(b1));
}

// ---------------------------------------------------------------------------
// K0: fp32 -> fp16 (round-to-nearest) conversion
// ---------------------------------------------------------------------------
__global__ __launch_bounds__(256) void k0_half(
    const float* __restrict__ src, __half* __restrict__ hi, size_t n4)
{
    size_t i = (size_t)blockIdx.x * 256 + threadIdx.x;
    if (i >= n4) return;
    float4 v = *(const float4*)(src + i * 4);
    __half h[4];
    h[0] = __float2half_rn(v.x); h[1] = __float2half_rn(v.y);
    h[2] = __float2half_rn(v.z); h[3] = __float2half_rn(v.w);
    *(uint2*)(hi + i * 4) = *(uint2*)h;
}

// ---------------------------------------------------------------------------
// K1: gi = xhi @ whi^T  -- single fp16 HMMA product (flag-and-fix repairs the
// residual exactly where argmax could flip; output rel_err stays ~3.6e-4).
// CTA 128x128, double-buffered cp.async (2 stages x 2 buffers = 40KB ->
// 2 CTAs/SM), one __syncthreads per stage.
// ---------------------------------------------------------------------------
#define BK 32
#define ROWB 80
#define TILEB (128 * ROWB)        // 10240
#define STAGEB (2 * TILEB)        // 20480 (A_hi, B_hi)
#define K1_SMEM (2 * STAGEB)      // 40960
#define NS (I_ / BK)              // 64

__global__ void __launch_bounds__(256, 2) k1_mma(
    const __half* __restrict__ xhi, const __half* __restrict__ whi)
{
    extern __shared__ char smem[];
    const uint32_t sbase = smem_u32(smem);
    const int tid = threadIdx.x;
    const int wid = tid >> 5;
    const int lane = tid & 31;

    const int t0 = blockIdx.x * 128;   // M
    const int c0 = blockIdx.y * 128;   // N

    const int warpM = (wid & 3) * 32;
    const int warpN = (wid >> 2) * 64;

    float acc[2][8][4];
#pragma unroll
    for (int i = 0; i < 2; i++)
#pragma unroll
        for (int j = 0; j < 8; j++)
#pragma unroll
            for (int q = 0; q < 4; q++) acc[i][j][q] = 0.f;

    auto fetch = [&](int s) {
        const int stg = s & 1;
        const uint32_t bA_hi = sbase + stg * STAGEB;
        const uint32_t bB_hi = bA_hi + TILEB;
        const int k0 = s * BK;
#pragma unroll
        for (int it = 0; it < 2; it++) {
            int c = it * 256 + tid;
            int kc = c >> 7;
            int row = c & 127;
            uint32_t so = (uint32_t)(row * ROWB + kc * 16);
            size_t ga = (size_t)(t0 + row) * I_ + k0 + kc * 8;
            size_t gb = (size_t)(c0 + row) * I_ + k0 + kc * 8;
            cp16(bA_hi + so, xhi + ga);
            cp16(bB_hi + so, whi + gb);
        }
    };

    fetch(0); CP_COMMIT();

    for (int s = 0; s < NS; s++) {
        CP_WAIT0();
        __syncthreads();

        if (s + 1 < NS) { fetch(s + 1); CP_COMMIT(); }

        const int stg = s & 1;
        const uint32_t bA_hi = sbase + stg * STAGEB;
        const uint32_t bB_hi = bA_hi + TILEB;

#pragma unroll
        for (int kc = 0; kc < 2; kc++) {
            const uint32_t kb = kc * 32 + (lane >> 4) * 16;
            const uint32_t rsel = (lane & 15);

            uint32_t Ah[2][4];
#pragma unroll
            for (int i = 0; i < 2; i++) {
                uint32_t off = (uint32_t)((warpM + i * 16 + rsel) * ROWB) + kb;
                ldsm_x4(Ah[i][0], Ah[i][1], Ah[i][2], Ah[i][3], bA_hi + off);
            }
#pragma unroll
            for (int g = 0; g < 4; g++) {
                uint32_t Bhg[4];
                uint32_t off = (uint32_t)((warpN + g * 16 + rsel) * ROWB) + kb;
                ldsm_x4(Bhg[0], Bhg[1], Bhg[2], Bhg[3], bB_hi + off);
#pragma unroll
                for (int i = 0; i < 2; i++) {
#pragma unroll
                    for (int sel = 0; sel < 2; sel++) {
                        const int j = g * 2 + sel;
                        mma16816(acc[i][j], Ah[i], Bhg[sel], Bhg[sel + 2]);
                    }
                }
            }
        }
    }

#pragma unroll
    for (int i = 0; i < 2; i++) {
#pragma unroll
        for (int j = 0; j < 8; j++) {
            int row = t0 + warpM + i * 16 + (lane >> 2);
            int col = c0 + warpN + j * 8 + (lane & 3) * 2;
            float2 u0 = make_float2(acc[i][j][0], acc[i][j][1]);
            float2 u1 = make_float2(acc[i][j][2], acc[i][j][3]);
            *(float2*)&g_gi[(size_t)row * NCOL + col] = u0;
            *(float2*)&g_gi[(size_t)(row + 8) * NCOL + col] = u1;
        }
    }
}

// ---------------------------------------------------------------------------
// gates: Hall[t][k][o]
// ---------------------------------------------------------------------------
__global__ __launch_bounds__(256) void k_gates(
    const float* __restrict__ bih, const float* __restrict__ bhh)
{
    size_t idx = (size_t)blockIdx.x * 256 + threadIdx.x;
    int o4 = (int)(idx % (HD / 4));
    int k  = (int)((idx / (HD / 4)) % K_);
    int t  = (int)(idx / ((size_t)K_ * (HD / 4)));

    const float* base = g_gi + (size_t)t * NCOL + (size_t)k * 3 * HD + o4 * 4;
    float4 ir4 = *(const float4*)(base);
    float4 iz4 = *(const float4*)(base + HD);
    float4 in4 = *(const float4*)(base + 2 * HD);

    const float* bi = bih + (size_t)k * 3 * HD;
    const float* bh = bhh + (size_t)k * 3 * HD;
    float4 br = *(const float4*)(bi + o4 * 4);
    float4 bz = *(const float4*)(bi + HD + o4 * 4);
    float4 bn = *(const float4*)(bi + 2 * HD + o4 * 4);
    float4 hr = *(const float4*)(bh + o4 * 4);
    float4 hz = *(const float4*)(bh + HD + o4 * 4);
    float4 hn = *(const float4*)(bh + 2 * HD + o4 * 4);

    float irs[4] = {ir4.x, ir4.y, ir4.z, ir4.w};
    float izs[4] = {iz4.x, iz4.y, iz4.z, iz4.w};
    float ins[4] = {in4.x, in4.y, in4.z, in4.w};
    float brs[4] = {br.x, br.y, br.z, br.w};
    float bzs[4] = {bz.x, bz.y, bz.z, bz.w};
    float bns[4] = {bn.x, bn.y, bn.z, bn.w};
    float hrs[4] = {hr.x, hr.y, hr.z, hr.w};
    float hzs[4] = {hz.x, hz.y, hz.z, hz.w};
    float hns[4] = {hn.x, hn.y, hn.z, hn.w};

    float res[4];
#pragma unroll
    for (int n = 0; n < 4; n++) {
        float r = 1.0f / (1.0f + expf(-(irs[n] + brs[n] + hrs[n])));
        float z = 1.0f / (1.0f + expf(-(izs[n] + bzs[n] + hzs[n])));
        float nn = tanhf(ins[n] + bns[n] + r * hns[n]);
        res[n] = (1.0f - z) * nn;
    }
    float4 o;
    o.x = res[0]; o.y = res[1]; o.z = res[2]; o.w = res[3];
    *(float4*)&g_Hall[((size_t)t * K_ + k) * HD + o4 * 4] = o;
}

// ---------------------------------------------------------------------------
// K2: D + sel_x
// ---------------------------------------------------------------------------
__global__ __launch_bounds__(256) void k2_Dselx(
    const float* __restrict__ xs, const float* __restrict__ Wsel,
    const float* __restrict__ bsel)
{
    const int t = blockIdx.x;
    float aD[9] = {0.f, 0.f, 0.f, 0.f, 0.f, 0.f, 0.f, 0.f, 0.f};
    float aS[3] = {0.f, 0.f, 0.f};

    const float* hrow = g_Hall + (size_t)t * K_ * HD;
    const float* xrow = xs + (size_t)t * I_;

    for (int h = threadIdx.x; h < HD; h += 256) {
        float w0 = Wsel[0 * WS_ + h];
        float w1 = Wsel[1 * WS_ + h];
        float w2 = Wsel[2 * WS_ + h];
#pragma unroll
        for (int j = 0; j < 3; j++) {
            float hv = hrow[(size_t)j * HD + h];
            aD[j * 3 + 0] = fmaf(hv, w0, aD[j * 3 + 0]);
            aD[j * 3 + 1] = fmaf(hv, w1, aD[j * 3 + 1]);
            aD[j * 3 + 2] = fmaf(hv, w2, aD[j * 3 + 2]);
        }
    }
    for (int i = threadIdx.x; i < I_; i += 256) {
        float xv = xrow[i];
        aS[0] = fmaf(xv, Wsel[0 * WS_ + HD + i], aS[0]);
        aS[1] = fmaf(xv, Wsel[1 * WS_ + HD + i], aS[1]);
        aS[2] = fmaf(xv, Wsel[2 * WS_ + HD + i], aS[2]);
    }

    float vals[12];
#pragma unroll
    for (int v = 0; v < 9; v++) vals[v] = aD[v];
#pragma unroll
    for (int v = 0; v < 3; v++) vals[9 + v] = aS[v];

    __shared__ float red[12][8];
    int lane = threadIdx.x & 31, w = threadIdx.x >> 5;
#pragma unroll
    for (int v = 0; v < 12; v++) {
        float s = vals[v];
        for (int off = 16; off > 0; off >>= 1)
            s += __shfl_down_sync(0xffffffffu, s, off);
        if (lane == 0) red[v][w] = s;
    }
    __syncthreads();
    if (threadIdx.x < 12) {
        float s = 0.f;
#pragma unroll
        for (int ww = 0; ww < 8; ww++) s += red[threadIdx.x][ww];
        if (threadIdx.x < 9)
            g_D[(size_t)t * 9 + threadIdx.x] = s;
        else
            g_selx[(size_t)t * 3 + (threadIdx.x - 9)] = s + bsel[threadIdx.x - 9];
    }
}

// ---------------------------------------------------------------------------
// reset fix counter (graph replays!)
// ---------------------------------------------------------------------------
__global__ void k_zero() { g_fixn = 0; }

// ---------------------------------------------------------------------------
// K3a: flag ambiguous steps (any j-row with top-2 gap < THETA) -> fixlist
// ---------------------------------------------------------------------------
__global__ void k3_flag()
{
    int t = blockIdx.x * blockDim.x + threadIdx.x;
    if (t < 1 || t >= T_) return;
    const float* d = g_D + (size_t)(t - 1) * 9;
    float s0 = g_selx[t * 3 + 0];
    float s1 = g_selx[t * 3 + 1];
    float s2 = g_selx[t * 3 + 2];
    bool amb = false;
#pragma unroll
    for (int j = 0; j < 3; j++) {
        float l0 = d[j * 3 + 0] + s0;
        float l1 = d[j * 3 + 1] + s1;
        float l2 = d[j * 3 + 2] + s2;
        float hi1 = fmaxf(l0, fmaxf(l1, l2));
        float lo1 = fminf(l0, fminf(l1, l2));
        float mid = l0 + l1 + l2 - hi1 - lo1;
        if (hi1 - mid < THETA) amb = true;
    }
    if (amb) {
        int idx = atomicAdd(&g_fixn, 1);
        if (idx < MAXF) g_fixlist[idx] = t - 1;   // D row to repair
    }
}

// ---------------------------------------------------------------------------
// K3b-fix1: batched full-residual GEMM for flagged rows.
// dfix[f][c] = sum_i ( x*w - rn16(x)*rn16(w) )   (repairs BOTH dropped terms)
// grid (NCOL/128, MAXF/32), block 256. smem-staged W and x chunks.
// ---------------------------------------------------------------------------
__global__ __launch_bounds__(256) void k_fixgemm(
    const float* __restrict__ xs, const float* __restrict__ Wih)
{
    int n = g_fixn; if (n > MAXF) n = MAXF;
    const int fbase = blockIdx.y * 32;
    if (fbase >= n) return;
    const int c0 = blockIdx.x * 128;
    const int tid = threadIdx.x;

    __shared__ float ws[32][129];    // [k][c]  exact w
    __shared__ float whs[32][129];   // [k][c]  rn16(w)
    __shared__ float xsm[32][33];    // [f][k]  exact x
    __shared__ float xhs[32][33];    // [f][k]  rn16(x)
    __shared__ int tlist[32];

    if (tid < 32) tlist[tid] = (fbase + tid < n) ? g_fixlist[fbase + tid] : -1;
    __syncthreads();

    const int c_loc = tid & 127;
    const int fgrp = (tid >> 7) * 16;

    float acc[16];
#pragma unroll
    for (int f = 0; f < 16; f++) acc[f] = 0.f;

    for (int kc0 = 0; kc0 < I_; kc0 += 32) {
        __syncthreads();
#pragma unroll
        for (int q = 0; q < 16; q++) {
            int lin = q * 256 + tid;          // 0..4095
            int c = lin >> 5, k = lin & 31;
            float w = Wih[(size_t)(c0 + c) * I_ + kc0 + k];
            ws[k][c] = w;
            whs[k][c] = __half2float(__float2half_rn(w));
        }
#pragma unroll
        for (int q = 0; q < 4; q++) {
            int lin = q * 256 + tid;          // 0..1023
            int f = lin >> 5, k = lin & 31;
            int t1 = tlist[f];
            float xv = (t1 >= 0) ? xs[(size_t)t1 * I_ + kc0 + k] : 0.f;
            xsm[f][k] = xv;
            xhs[f][k] = __half2float(__float2half_rn(xv));
        }
        __syncthreads();

#pragma unroll 4
        for (int k = 0; k < 32; k++) {
            float w = ws[k][c_loc];
            float wh = whs[k][c_loc];
#pragma unroll
            for (int f = 0; f < 16; f++) {
                acc[f] = fmaf(xsm[fgrp + f][k], w, acc[f]);
                acc[f] = fmaf(-xhs[fgrp + f][k], wh, acc[f]);
            }
        }
    }

#pragma unroll
    for (int f = 0; f < 16; f++) {
        int fg = fbase + fgrp + f;
        if (fg < n) g_dfix[(size_t)fg * NCOL + c0 + c_loc] = acc[f];
    }
}

// ---------------------------------------------------------------------------
// K3b-fix2: recompute exact D rows for flagged steps.  grid (MAXF, 3).
// ---------------------------------------------------------------------------
__global__ __launch_bounds__(256) void k_fixD(
    const float* __restrict__ Wsel,
    const float* __restrict__ bih, const float* __restrict__ bhh)
{
    int n = g_fixn; if (n > MAXF) n = MAXF;
    const int fi = blockIdx.x;
    if (fi >= n) return;
    const int t1 = g_fixlist[fi];
    const int j = blockIdx.y;
    const int tid = threadIdx.x;

    const size_t gb = (size_t)t1 * NCOL + (size_t)j * 3 * HD;
    const size_t db = (size_t)fi * NCOL + (size_t)j * 3 * HD;
    const float* bi = bih + (size_t)j * 3 * HD;
    const float* bh = bhh + (size_t)j * 3 * HD;

    float p0 = 0.f, p1 = 0.f, p2 = 0.f;
    for (int o = tid; o < HD; o += 256) {
        float ir  = g_gi[gb + o]          + g_dfix[db + o]          + bi[o]          + bh[o];
        float iz  = g_gi[gb + HD + o]     + g_dfix[db + HD + o]     + bi[HD + o]     + bh[HD + o];
        float inn = g_gi[gb + 2 * HD + o] + g_dfix[db + 2 * HD + o] + bi[2 * HD + o];
        float hn  = bh[2 * HD + o];
        float r = 1.0f / (1.0f + expf(-ir));
        float z = 1.0f / (1.0f + expf(-iz));
        float nn = tanhf(inn + r * hn);
        float h = (1.0f - z) * nn;
        p0 = fmaf(Wsel[0 * WS_ + o], h, p0);
        p1 = fmaf(Wsel[1 * WS_ + o], h, p1);
        p2 = fmaf(Wsel[2 * WS_ + o], h, p2);
    }

    __shared__ float red[3][8];
    int lane = tid & 31, w = tid >> 5;
    float v[3] = {p0, p1, p2};
#pragma unroll
    for (int q = 0; q < 3; q++) {
        float s = v[q];
        for (int off = 16; off > 0; off >>= 1)
            s += __shfl_down_sync(0xffffffffu, s, off);
        if (lane == 0) red[q][w] = s;
    }
    __syncthreads();
    if (tid < 3) {
        float s = 0.f;
#pragma unroll
        for (int ww = 0; ww < 8; ww++) s += red[tid][ww];
        g_D[(size_t)t1 * 9 + j * 3 + tid] = s;
    }
}

// ---------------------------------------------------------------------------
// K3: packed transition maps (after D repair)
// ---------------------------------------------------------------------------
__global__ void k3_f()
{
    int t = blockIdx.x * blockDim.x + threadIdx.x;
    if (t < 1 || t >= T_) return;
    const float* d = g_D + (size_t)(t - 1) * 9;
    float s0 = g_selx[t * 3 + 0];
    float s1 = g_selx[t * 3 + 1];
    float s2 = g_selx[t * 3 + 2];
    unsigned int word = 0;
#pragma unroll
    for (int j = 0; j < 3; j++) {
        float l0 = d[j * 3 + 0] + s0;
        float l1 = d[j * 3 + 1] + s1;
        float l2 = d[j * 3 + 2] + s2;
        int best = 0; float bv = l0;
        if (l1 > bv) { bv = l1; best = 1; }
        if (l2 > bv) { best = 2; }
        word |= (unsigned int)best << (8 * j);
    }
    g_fw[t] = word;
}

// ---------------------------------------------------------------------------
// K4: sequential 3-state automaton composition
// ---------------------------------------------------------------------------
__global__ __launch_bounds__(256) void k4_scan()
{
    __shared__ unsigned int sw[T_];
    for (int i = threadIdx.x; i < T_; i += 256) sw[i] = g_fw[i];
    __syncthreads();
    if (threadIdx.x == 0) {
        int cur = 0;
        g_kk[0] = 0;
        for (int t = 1; t < T_; t++) {
            unsigned int w = sw[t];
            cur = (int)((w >> (cur << 3)) & 0xffu);
            g_kk[t] = cur;
        }
    }
}

// ---------------------------------------------------------------------------
// K5: gather
// ---------------------------------------------------------------------------
__global__ __launch_bounds__(256) void k5_gather(float* __restrict__ out)
{
    int t = blockIdx.x;
    int tt = (t == T_) ? (T_ - 1) : t;
    int sel = g_kk[tt];
    const float4* src = (const float4*)(g_Hall + ((size_t)tt * K_ + sel) * HD);
    float4* dst = (float4*)(out + (size_t)t * HD);
    for (int i = threadIdx.x; i < HD / 4; i += 256) dst[i] = src[i];
}

// ---------------------------------------------------------------------------
extern "C" void kernel_launch(void* const* d_in, const int* in_sizes, int n_in,
                              void* d_out, int out_size)
{
    const float* x    = (const float*)d_in[0];
    const float* Wih  = (const float*)d_in[1];
    // d_in[2] = W_hh : unused (only b_hh enters the math)
    const float* bih  = (const float*)d_in[3];
    const float* bhh  = (const float*)d_in[4];
    const float* Wsel = (const float*)d_in[5];
    const float* bsel = (const float*)d_in[6];
    float* out = (float*)d_out;

    __half *xhi, *whi;
    cudaGetSymbolAddress((void**)&xhi, g_xhi);
    cudaGetSymbolAddress((void**)&whi, g_whi);

    cudaFuncSetAttribute(k1_mma, cudaFuncAttributeMaxDynamicSharedMemorySize, K1_SMEM);

    size_t nx4 = (size_t)T_ * I_ / 4;
    size_t nw4 = (size_t)NCOL * I_ / 4;
    k0_half<<<(int)((nx4 + 255) / 256), 256>>>(x, xhi, nx4);
    k0_half<<<(int)((nw4 + 255) / 256), 256>>>(Wih, whi, nw4);

    dim3 g1(T_ / 128, NCOL / 128);  // M-fast -> A stays L2-resident
    k1_mma<<<g1, 256, K1_SMEM>>>(xhi, whi);

    k_gates<<<(int)(((size_t)T_ * K_ * (HD / 4)) / 256), 256>>>(bih, bhh);
    k2_Dselx<<<T_, 256>>>(x, Wsel, bsel);

    k_zero<<<1, 1>>>();
    k3_flag<<<(T_ + 255) / 256, 256>>>();
    {
        dim3 gf(NCOL / 128, MAXF / 32);
        k_fixgemm<<<gf, 256>>>(x, Wih);
    }
    {
        dim3 gd(MAXF, 3);
        k_fixD<<<gd, 256>>>(Wsel, bih, bhh);
    }
    k3_f<<<(T_ + 255) / 256, 256>>>();
    k4_scan<<<1, 256>>>();
    k5_gather<<<T_ + 1, 256>>>(out);
}